// round 5
// baseline (speedup 1.0000x reference)
#include <cuda_runtime.h>
#include <math.h>

#define Bn 32
#define Tn 512
#define Hn 2048
#define Kn 128

// Scratch (no allocations allowed)
__device__ float g_logits[Bn * Tn * Kn];   // 8 MB
__device__ float g_llh[Bn];

// ---------------------------------------------------------------------------
// GEMM: logits[m][n] = sum_h hiddens[m][h] * W[h][n] + b[n]
// M = 16384, N = 128, H = 2048.  BM=32, BN=128, BK=16, 256 threads,
// 4x4 per-thread tile, grid = 512 (-> ~3.5 blocks/SM for latency hiding).
// Per-output accumulation order identical to R1 (k ascending) -> bit-exact.
// ---------------------------------------------------------------------------
__global__ __launch_bounds__(256) void gemm_kernel(
    const float* __restrict__ hid, const float* __restrict__ W,
    const float* __restrict__ bias)
{
    __shared__ float As[16][36];    // transposed A tile, padded (bank spread)
    __shared__ float Bs[16][128];

    const int tid = threadIdx.x;
    const int m0  = blockIdx.x * 32;
    const int ty4 = (tid >> 5) * 4;   // 4-row group per warp
    const int tx  = tid & 31;         // 4-col group per lane

    float acc[4][4];
#pragma unroll
    for (int r = 0; r < 4; r++)
#pragma unroll
        for (int q = 0; q < 4; q++) acc[r][q] = 0.f;

    const int arow = tid >> 3;            // 0..31
    const int ac2  = (tid & 7) * 2;       // 0,2,..,14
    const float* Arow = hid + (size_t)(m0 + arow) * Hn + ac2;
    const int br = tid >> 5;              // 0..7
    const int bc4 = (tid & 31) * 4;

    for (int k0 = 0; k0 < Hn; k0 += 16) {
        float2 a2 = *(const float2*)(Arow + k0);
        As[ac2 + 0][arow] = a2.x;
        As[ac2 + 1][arow] = a2.y;
        *(float4*)(&Bs[br][bc4]) =
            *(const float4*)(W + (size_t)(k0 + br) * Kn + bc4);
        *(float4*)(&Bs[br + 8][bc4]) =
            *(const float4*)(W + (size_t)(k0 + br + 8) * Kn + bc4);
        __syncthreads();

#pragma unroll
        for (int k = 0; k < 16; k++) {
            float4 b4 = *(const float4*)(&Bs[k][tx * 4]);
            float4 a4 = *(const float4*)(&As[k][ty4]);
            acc[0][0] += a4.x * b4.x; acc[0][1] += a4.x * b4.y;
            acc[0][2] += a4.x * b4.z; acc[0][3] += a4.x * b4.w;
            acc[1][0] += a4.y * b4.x; acc[1][1] += a4.y * b4.y;
            acc[1][2] += a4.y * b4.z; acc[1][3] += a4.y * b4.w;
            acc[2][0] += a4.z * b4.x; acc[2][1] += a4.z * b4.y;
            acc[2][2] += a4.z * b4.z; acc[2][3] += a4.z * b4.w;
            acc[3][0] += a4.w * b4.x; acc[3][1] += a4.w * b4.y;
            acc[3][2] += a4.w * b4.z; acc[3][3] += a4.w * b4.w;
        }
        __syncthreads();
    }

    const int n0 = tx * 4;
    float4 bb = *(const float4*)(bias + n0);
#pragma unroll
    for (int r = 0; r < 4; r++) {
        int row = m0 + ty4 + r;
        float4 o;
        o.x = acc[r][0] + bb.x;
        o.y = acc[r][1] + bb.y;
        o.z = acc[r][2] + bb.z;
        o.w = acc[r][3] + bb.w;
        *(float4*)(g_logits + (size_t)row * Kn + n0) = o;
    }
}

// ---------------------------------------------------------------------------
// CRF recurrences. 64 blocks x 256 threads.
// blocks [0,32): forward logsumexp + path score -> g_llh[b]
// blocks [32,64): viterbi decode -> out[b*T .. ] (tags as float)
// Thread mapping: j = tid>>1 (tag column), h = tid&1 (row half).
// ---------------------------------------------------------------------------
#define SMEM_BYTES (1024 + (Tn - 1) * Kn)

__global__ __launch_bounds__(256) void crf_kernel(
    const int* __restrict__ mask, const int* __restrict__ labels,
    const float* __restrict__ startT, const float* __restrict__ endT,
    const float* __restrict__ trans, float* __restrict__ out)
{
    extern __shared__ char smem[];
    float* sh_s  = (float*)smem;                 // 128 floats
    float* shred = (float*)(smem + 512);         // reduce scratch (floats)
    int*   shredi = (int*)(smem + 512 + 256);    // reduce scratch (ints)
    unsigned char* bp = (unsigned char*)(smem + 1024); // 511*128 bytes

    const int tid = threadIdx.x;
    const int j = tid >> 1, h = tid & 1;
    const unsigned FULL = 0xFFFFFFFFu;
    const int bidx = blockIdx.x;

    if (bidx < Bn) {
        // ================= FORWARD =================
        const int b = bidx;
        float Eh[64];
#pragma unroll
        for (int i = 0; i < 64; i++)
            Eh[i] = expf(trans[(h * 64 + i) * Kn + j]);

        const float* lg = g_logits + (size_t)b * Tn * Kn;
        float alpha = startT[j] + lg[j];
        float e_next = lg[Kn + j];

        for (int t = 1; t < Tn; t++) {
            float emit = e_next;
            if (t + 1 < Tn) e_next = lg[(size_t)(t + 1) * Kn + j];
            int mt = mask[b * Tn + t];

            // block max of alpha
            float wm = alpha;
#pragma unroll
            for (int o = 16; o; o >>= 1)
                wm = fmaxf(wm, __shfl_xor_sync(FULL, wm, o));
            if ((tid & 31) == 0) shred[tid >> 5] = wm;
            __syncthreads();                       // S1
            float m = shred[0];
#pragma unroll
            for (int w = 1; w < 8; w++) m = fmaxf(m, shred[w]);

            float p = expf(alpha - m);
            if (h == 0) sh_s[j] = p;
            __syncthreads();                       // S2

            float s = 0.f;
            const float4* p4 = (const float4*)(sh_s + h * 64);
#pragma unroll
            for (int i4 = 0; i4 < 16; i4++) {
                float4 v = p4[i4];
                s += v.x * Eh[i4 * 4 + 0];
                s += v.y * Eh[i4 * 4 + 1];
                s += v.z * Eh[i4 * 4 + 2];
                s += v.w * Eh[i4 * 4 + 3];
            }
            s += __shfl_xor_sync(FULL, s, 1);
            float nxt = m + logf(s) + emit;
            alpha = (mt > 0) ? nxt : alpha;
        }

        // logZ = logsumexp_j(alpha_j + end_j)
        __syncthreads();
        float v = alpha + endT[j];
        float wm = v;
#pragma unroll
        for (int o = 16; o; o >>= 1)
            wm = fmaxf(wm, __shfl_xor_sync(FULL, wm, o));
        if ((tid & 31) == 0) shred[tid >> 5] = wm;
        __syncthreads();
        float m = shred[0];
#pragma unroll
        for (int w = 1; w < 8; w++) m = fmaxf(m, shred[w]);
        __syncthreads();
        float pc = (h == 0) ? expf(v - m) : 0.f;
#pragma unroll
        for (int o = 16; o; o >>= 1)
            pc += __shfl_xor_sync(FULL, pc, o);
        if ((tid & 31) == 0) shred[tid >> 5] = pc;
        __syncthreads();
        float Z = 0.f;
#pragma unroll
        for (int w = 0; w < 8; w++) Z += shred[w];
        float logZ = m + logf(Z);
        __syncthreads();

        // path score
        float sc = 0.f;
        int msum = 0;
        for (int t = tid; t < Tn; t += 256) {
            msum += mask[b * Tn + t];
            if (t >= 1) {
                int cur  = labels[b * Tn + t];
                int prev = labels[b * Tn + t - 1];
                float mf = (float)mask[b * Tn + t];
                sc += (trans[prev * Kn + cur] + lg[(size_t)t * Kn + cur]) * mf;
            }
        }
#pragma unroll
        for (int o = 16; o; o >>= 1) {
            sc   += __shfl_xor_sync(FULL, sc, o);
            msum += __shfl_xor_sync(FULL, msum, o);
        }
        if ((tid & 31) == 0) { shred[tid >> 5] = sc; shredi[tid >> 5] = msum; }
        __syncthreads();
        if (tid == 0) {
            float S = 0.f; int M = 0;
#pragma unroll
            for (int w = 0; w < 8; w++) { S += shred[w]; M += shredi[w]; }
            int l0 = labels[b * Tn];
            S += startT[l0] + lg[l0];
            int last = labels[b * Tn + (M - 1)];
            S += endT[last];
            g_llh[b] = S - logZ;
        }
    } else {
        // ================= VITERBI =================
        const int b = bidx - Bn;
        float Th[64];                 // register-resident (static indices only)
#pragma unroll
        for (int i = 0; i < 64; i++)
            Th[i] = trans[(h * 64 + i) * Kn + j];
        // deliberate local-memory shadow for dynamic pass-2 indexing
        float lth[64];
#pragma unroll
        for (int i = 0; i < 64; i++)
            lth[i] = trans[(h * 64 + i) * Kn + j];

        const float* lg = g_logits + (size_t)b * Tn * Kn;
        float sj = startT[j] + lg[j];
        if (h == 0) sh_s[j] = sj;
        float e_next = lg[Kn + j];
        __syncthreads();

        for (int t = 1; t < Tn; t++) {
            float emit = e_next;
            if (t + 1 < Tn) e_next = lg[(size_t)(t + 1) * Kn + j];
            int mt = mask[b * Tn + t];

            // ---- pass 1: value-only max over 8 groups of 8 (FADD+FMNMX) ----
            const float4* s4 = (const float4*)(sh_s + h * 64);
            float best = -3.4e38f;
            int bg = 0;
#pragma unroll
            for (int g = 0; g < 8; g++) {
                float4 v0 = s4[2 * g];
                float4 v1 = s4[2 * g + 1];
                float c0 = v0.x + Th[8 * g + 0];
                float c1 = v0.y + Th[8 * g + 1];
                float c2 = v0.z + Th[8 * g + 2];
                float c3 = v0.w + Th[8 * g + 3];
                float c4 = v1.x + Th[8 * g + 4];
                float c5 = v1.y + Th[8 * g + 5];
                float c6 = v1.z + Th[8 * g + 6];
                float c7 = v1.w + Th[8 * g + 7];
                float gm = fmaxf(fmaxf(fmaxf(c0, c1), fmaxf(c2, c3)),
                                 fmaxf(fmaxf(c4, c5), fmaxf(c6, c7)));
                if (gm > best) { best = gm; bg = g; }   // ties -> first group
            }

            // ---- pass 2: exact-equality index scan in winning group ----
            const float* sv = sh_s + h * 64 + bg * 8;
            int aq = 0;
#pragma unroll
            for (int q = 7; q >= 0; q--) {              // descending: first wins
                float c = sv[q] + lth[bg * 8 + q];
                if (c == best) aq = q;
            }
            int ai = h * 64 + bg * 8 + aq;

            // cross-h combine; h==0 wins ties (lower global index)
            float ob = __shfl_xor_sync(FULL, best, 1);
            int   oi = __shfl_xor_sync(FULL, ai, 1);
            float lb = (h == 0) ? best : ob;
            int   li = (h == 0) ? ai   : oi;
            float hb = (h == 0) ? ob   : best;
            int   hi = (h == 0) ? oi   : ai;
            float fb; int fa;
            if (hb > lb) { fb = hb; fa = hi; } else { fb = lb; fa = li; }

            float ns; int bpv;
            if (mt > 0) { ns = fb + emit; bpv = fa; }
            else        { ns = sj;        bpv = j;  }
            sj = ns;
            __syncthreads();                       // S1 (reads done)
            if (h == 0) {
                sh_s[j] = sj;
                bp[(size_t)(t - 1) * Kn + j] = (unsigned char)bpv;
            }
            __syncthreads();                       // S2 (writes visible)
        }

        if (h == 0) sh_s[j] = sj + endT[j];
        __syncthreads();
        if (tid == 0) {
            float bbest = sh_s[0];
            int btag = 0;
            for (int q = 1; q < Kn; q++) {
                float vv = sh_s[q];
                if (vv > bbest) { bbest = vv; btag = q; }
            }
            int tag = btag;
            out[b * Tn + (Tn - 1)] = (float)tag;
            for (int t = Tn - 2; t >= 0; t--) {
                tag = bp[(size_t)t * Kn + tag];
                out[b * Tn + t] = (float)tag;
            }
        }
    }
}

// ---------------------------------------------------------------------------
// loss = -mean(llh)
// ---------------------------------------------------------------------------
__global__ void loss_kernel(float* __restrict__ out)
{
    const unsigned FULL = 0xFFFFFFFFu;
    float v = (threadIdx.x < Bn) ? g_llh[threadIdx.x] : 0.f;
#pragma unroll
    for (int o = 16; o; o >>= 1) v += __shfl_xor_sync(FULL, v, o);
    if (threadIdx.x == 0) out[Bn * Tn] = -(v / (float)Bn);
}

extern "C" void kernel_launch(void* const* d_in, const int* in_sizes, int n_in,
                              void* d_out, int out_size)
{
    const float* hiddens = (const float*)d_in[0];
    const int*   mask    = (const int*)d_in[1];
    const int*   labels  = (const int*)d_in[2];
    const float* W       = (const float*)d_in[3];
    const float* bias    = (const float*)d_in[4];
    const float* startT  = (const float*)d_in[5];
    const float* endT    = (const float*)d_in[6];
    const float* trans   = (const float*)d_in[7];
    float* out = (float*)d_out;

    gemm_kernel<<<(Bn * Tn) / 32, 256>>>(hiddens, W, bias);

    cudaFuncSetAttribute(crf_kernel, cudaFuncAttributeMaxDynamicSharedMemorySize,
                         SMEM_BYTES);
    crf_kernel<<<2 * Bn, 256, SMEM_BYTES>>>(mask, labels, startT, endT, trans, out);

    loss_kernel<<<1, 32>>>(out);
}